// round 13
// baseline (speedup 1.0000x reference)
#include <cuda_runtime.h>
#include <math.h>

// Problem constants
#define NUM_R 8
#define KLEN  128
#define HID   32
#define LREC  4096
#define KP1   (KLEN + 1)
#define MAXB1 16

// Base table (kb==128 coefficients): g_T[b1][r][h] = (vy*(A + inv*B), vy*A)
//   where A = PA[128], B = PB[128]. Contribution = t.x + u * t.y.
__device__ float2 g_T[MAXB1][NUM_R][HID];
// Raw prefix tables (PA, PB): corrections + general fallback
__device__ float  g_P[NUM_R][KP1][2][HID];
// vy[b1][r]
__device__ float  g_vy[MAXB1][NUM_R];

// Table build: one block per (b1, r), smem scratch for prefix sums.
// Only b1==0 blocks write g_P (it depends on r only).
__global__ void __launch_bounds__(256) prep_kernel(
    const float* __restrict__ W1, const float* __restrict__ rec)
{
    __shared__ float sA[KP1][HID];
    __shared__ float sB[KP1][HID];
    __shared__ float sTA[8][HID];
    __shared__ float sTB[8][HID];
    int r   = blockIdx.x & (NUM_R - 1);
    int b1  = blockIdx.x >> 3;
    int h   = threadIdx.x & 31;
    int seg = threadIdx.x >> 5;   // 0..7, 16 k's each
    const float inv = 1.0f / 16384.0f;

    int k0 = seg * 16;
    float a = 0.f, b = 0.f;
    if (seg == 0) { sA[0][h] = 0.f; sB[0][h] = 0.f; }
#pragma unroll
    for (int j = 0; j < 16; ++j) {
        int k = k0 + j;
        float w = W1[(r * KLEN + k) * HID + h];
        a += w;
        b += (float)k * w;
        sA[k + 1][h] = a;
        sB[k + 1][h] = b;
    }
    sTA[seg][h] = a;
    sTB[seg][h] = b;
    __syncthreads();

    float offA = 0.f, offB = 0.f;
    for (int s = 0; s < seg; ++s) { offA += sTA[s][h]; offB += sTB[s][h]; }
    if (seg > 0) {
#pragma unroll
        for (int j = 0; j < 16; ++j) {
            int k = k0 + j;
            sA[k + 1][h] += offA;
            sB[k + 1][h] += offB;
        }
    }
    __syncthreads();

    const float* rr = rec + (size_t)(b1 * NUM_R + r) * LREC;
    float vy = 0.5f * rr[2047] + 0.5f * rr[2048];
    if (threadIdx.x == 0) g_vy[b1][r] = vy;

    if (b1 == 0) {
        for (int k = seg; k < KP1; k += 8) {
            g_P[r][k][0][h] = sA[k][h];
            g_P[r][k][1][h] = sB[k][h];
        }
    }
    if (seg == 0) {
        float Aend = sA[KLEN][h];
        float Bend = sB[KLEN][h];
        g_T[b1][r][h] = make_float2(vy * fmaf(inv, Bend, Aend), vy * Aend);
    }
    // Signal PDL dependents (tof) that our global stores are ready.
    asm volatile("griddepcontrol.launch_dependents;" ::: "memory");
}

// Warp-autonomous main kernel: each warp owns 8 samples = 2 tiles of 4.
// Fast path: kb==128 base coefficients in registers (from tiny g_T);
// per sample only smem u's + 8 FMA. Rare kb<128 pairs fixed via ballot loop
// using exact deltas computed from the raw prefix tables.
__global__ void __launch_bounds__(256) tof_kernel(
    const float* __restrict__ sloc,   // (B1*B2, 3)
    const float* __restrict__ emit,   // (3,)
    const float* __restrict__ rloc,   // (R, 3)
    const float* __restrict__ b1v,    // (HID,)
    const float* __restrict__ W2,     // (HID,)
    const float* __restrict__ b2v,    // (1,)
    float* __restrict__ out,          // (B1*B2,)
    int total, int b2n, int b1shift)
{
    __shared__ __align__(16) float su[8][2][4][NUM_R];

    int tid  = threadIdx.x;
    int wid  = tid >> 5;
    int lane = tid & 31;
    int s_loc = lane >> 3;
    int r     = lane & 7;
    int s_base = ((int)blockIdx.x * 8 + wid) * 8;
    const float inv  = 1.0f / 16384.0f;
    const float inv2 = 2.0f / 16384.0f;
    const float SCALE = 96000.0f / 343.0f;

    int b1w = (b1shift >= 0) ? (s_base >> b1shift)
                             : (int)((unsigned)s_base / (unsigned)b2n);

    // ---- Phase 1: issue ALL coordinate loads first (max MLP) ----
    float cxv[2], cyv[2], czv[2];
    bool  vv[2];
#pragma unroll
    for (int t = 0; t < 2; ++t) {
        int s = s_base + t * 4 + s_loc;
        vv[t] = s < total;
        cxv[t] = 0.f; cyv[t] = 0.f; czv[t] = 0.f;
        if (vv[t]) {
            const float* p = sloc + (size_t)s * 3;
            cxv[t] = p[0]; cyv[t] = p[1]; czv[t] = p[2];
        }
    }
    float ex = emit[0], ey = emit[1], ez = emit[2];
    const float* rp = rloc + r * 3;
    float rx = rp[0], ry = rp[1], rz = rp[2];
    float blane = b1v[lane];
    float wlane = W2[lane];
    float b2s   = b2v[0];

    // ---- geometry per tile ----
    bool ok = true;
    bool corr[2];
#pragma unroll
    for (int t = 0; t < 2; ++t) {
        float uv = 0.f;
        corr[t] = false;
        if (vv[t]) {
            int s = s_base + t * 4 + s_loc;
            float dx = cxv[t] - ex, dy = cyv[t] - ey, dz = czv[t] - ez;
            float de = sqrtf(dx * dx + dy * dy + dz * dz);
            float qx = cxv[t] - rx, qy = cyv[t] - ry, qz = czv[t] - rz;
            float dr = sqrtf(qx * qx + qy * qy + qz * qz);
            int cs = (int)rintf((de + dr) * SCALE) - (KLEN / 2);
            int m0 = 4 * cs - 8192;
            int b1 = (b1shift >= 0) ? (s >> b1shift)
                                    : (int)((unsigned)s / (unsigned)b2n);
            ok = ok && (m0 >= -16384) && (m0 <= 16384 - KLEN) && (b1 == b1w);
            corr[t] = (m0 > -KLEN);          // kb != 128
            uv = (float)m0 * inv;
        }
        su[wid][t][s_loc][r] = uv;
    }
    bool fast = __all_sync(0xffffffffu, ok);
    unsigned bal0 = __ballot_sync(0xffffffffu, corr[0]);
    unsigned bal1 = __ballot_sync(0xffffffffu, corr[1]);
    __syncwarp();
    // Wait for prep's tables (PDL). No-op when launched without PDL.
    asm volatile("griddepcontrol.wait;" ::: "memory");

    if (fast) {
        // ---- preload kb=128 base coefficients (tiny table, L1-hot) ----
        float CY[NUM_R];
        float CX = 0.f;
#pragma unroll
        for (int rr = 0; rr < NUM_R; ++rr) {
            float2 tb = g_T[b1w][rr][lane];
            CX += tb.x;
            CY[rr] = tb.y;
        }

#pragma unroll
        for (int t = 0; t < 2; ++t) {
            int s0g = s_base + t * 4;
            const float4* u4 = (const float4*)&su[wid][t][0][0]; // 2 per sample
            float4 a0 = u4[0], a1 = u4[1];
            float4 b0 = u4[2], b1_ = u4[3];
            float4 c0_ = u4[4], c1_ = u4[5];
            float4 d0 = u4[6], d1 = u4[7];

            float acc0 = CX, acc1 = CX, acc2 = CX, acc3 = CX;
            acc0 = fmaf(a0.x, CY[0], acc0); acc0 = fmaf(a0.y, CY[1], acc0);
            acc0 = fmaf(a0.z, CY[2], acc0); acc0 = fmaf(a0.w, CY[3], acc0);
            acc0 = fmaf(a1.x, CY[4], acc0); acc0 = fmaf(a1.y, CY[5], acc0);
            acc0 = fmaf(a1.z, CY[6], acc0); acc0 = fmaf(a1.w, CY[7], acc0);
            acc1 = fmaf(b0.x, CY[0], acc1); acc1 = fmaf(b0.y, CY[1], acc1);
            acc1 = fmaf(b0.z, CY[2], acc1); acc1 = fmaf(b0.w, CY[3], acc1);
            acc1 = fmaf(b1_.x, CY[4], acc1); acc1 = fmaf(b1_.y, CY[5], acc1);
            acc1 = fmaf(b1_.z, CY[6], acc1); acc1 = fmaf(b1_.w, CY[7], acc1);
            acc2 = fmaf(c0_.x, CY[0], acc2); acc2 = fmaf(c0_.y, CY[1], acc2);
            acc2 = fmaf(c0_.z, CY[2], acc2); acc2 = fmaf(c0_.w, CY[3], acc2);
            acc2 = fmaf(c1_.x, CY[4], acc2); acc2 = fmaf(c1_.y, CY[5], acc2);
            acc2 = fmaf(c1_.z, CY[6], acc2); acc2 = fmaf(c1_.w, CY[7], acc2);
            acc3 = fmaf(d0.x, CY[0], acc3); acc3 = fmaf(d0.y, CY[1], acc3);
            acc3 = fmaf(d0.z, CY[2], acc3); acc3 = fmaf(d0.w, CY[3], acc3);
            acc3 = fmaf(d1.x, CY[4], acc3); acc3 = fmaf(d1.y, CY[5], acc3);
            acc3 = fmaf(d1.z, CY[6], acc3); acc3 = fmaf(d1.w, CY[7], acc3);

            // ---- rare corrections: pairs with kb != 128 ----
            unsigned bal = (t == 0) ? bal0 : bal1;
            while (bal) {
                int bpos = __ffs(bal) - 1;
                bal &= bal - 1;
                int sj = bpos >> 3;
                int rr = bpos & 7;
                float u = su[wid][t][sj][rr];
                int m0 = __float2int_rn(u * 16384.0f);   // exact recovery
                int kb = max(min(-m0, KLEN), 0);
                float dPA = g_P[rr][kb][0][lane] - g_P[rr][KLEN][0][lane];
                float dPB = g_P[rr][kb][1][lane] - g_P[rr][KLEN][1][lane];
                float vy  = g_vy[b1w][rr];
                float dlt = vy * fmaf(u * 2.0f, dPA, inv2 * dPB);
                acc0 += (sj == 0) ? dlt : 0.f;
                acc1 += (sj == 1) ? dlt : 0.f;
                acc2 += (sj == 2) ? dlt : 0.f;
                acc3 += (sj == 3) ? dlt : 0.f;
            }

            // relu + W2 dot, merged 4-sample warp reduction (proven form:
            // all shuffles unconditional; ternaries select lane-local sums)
            float c0 = fmaxf(acc0 + blane, 0.f) * wlane;
            float c1 = fmaxf(acc1 + blane, 0.f) * wlane;
            float c2 = fmaxf(acc2 + blane, 0.f) * wlane;
            float c3 = fmaxf(acc3 + blane, 0.f) * wlane;

            float t0 = __shfl_xor_sync(0xffffffffu, c0, 16);
            float t1 = __shfl_xor_sync(0xffffffffu, c1, 16);
            float t2 = __shfl_xor_sync(0xffffffffu, c2, 16);
            float t3 = __shfl_xor_sync(0xffffffffu, c3, 16);
            bool lo16 = lane < 16;
            float v = lo16 ? (c0 + t0) : (c1 + t1);
            float w = lo16 ? (c2 + t2) : (c3 + t3);
            float tv = __shfl_xor_sync(0xffffffffu, v, 8);
            float tw = __shfl_xor_sync(0xffffffffu, w, 8);
            float z = ((lane & 8) == 0) ? (v + tv) : (w + tw);
            z += __shfl_xor_sync(0xffffffffu, z, 4);
            z += __shfl_xor_sync(0xffffffffu, z, 2);
            z += __shfl_xor_sync(0xffffffffu, z, 1);

            if ((lane & 7) == 0) {
                int g = ((lane >> 2) & 2) | (lane >> 4); // 0->0,8->2,16->1,24->3
                int idx = s0g + g;
                if (idx < total) out[idx] = z + b2s;
            }
        }
    } else {
        // ---- General fallback (rare): full clamped two-segment form ----
#pragma unroll
        for (int t = 0; t < 2; ++t) {
            int s0g = s_base + t * 4;
            float accs[4];
            for (int j = 0; j < 4; ++j) {
                accs[j] = 0.f;
                int sample = s0g + j;
                if (sample >= total) continue;
                int b1 = (b1shift >= 0) ? (sample >> b1shift)
                                        : (int)((unsigned)sample / (unsigned)b2n);
                float a = 0.f;
                for (int rr = 0; rr < NUM_R; ++rr) {
                    float u = su[wid][t][j][rr];
                    int m0 = __float2int_rn(u * 16384.0f);
                    float vy = g_vy[b1][rr];
                    int ka = max(min(-16384 - m0, KLEN), 0);
                    int kb = max(min(-m0,          KLEN), 0);
                    int kd = max(min(16384 - m0,   KLEN), 0);
                    float m0f = (float)m0;
                    if (kb > ka) {
                        float pa = g_P[rr][kb][0][lane] - g_P[rr][ka][0][lane];
                        float pb = g_P[rr][kb][1][lane] - g_P[rr][ka][1][lane];
                        a += vy * (fmaf(m0f, inv, 1.0f) * pa + inv * pb);
                    }
                    if (kd > kb) {
                        float pa = g_P[rr][kd][0][lane] - g_P[rr][kb][0][lane];
                        float pb = g_P[rr][kd][1][lane] - g_P[rr][kb][1][lane];
                        a += vy * (fmaf(-m0f, inv, 1.0f) * pa - inv * pb);
                    }
                }
                accs[j] = a;
            }
            float c0 = fmaxf(accs[0] + blane, 0.f) * wlane;
            float c1 = fmaxf(accs[1] + blane, 0.f) * wlane;
            float c2 = fmaxf(accs[2] + blane, 0.f) * wlane;
            float c3 = fmaxf(accs[3] + blane, 0.f) * wlane;

            float t0 = __shfl_xor_sync(0xffffffffu, c0, 16);
            float t1 = __shfl_xor_sync(0xffffffffu, c1, 16);
            float t2 = __shfl_xor_sync(0xffffffffu, c2, 16);
            float t3 = __shfl_xor_sync(0xffffffffu, c3, 16);
            bool lo16 = lane < 16;
            float v = lo16 ? (c0 + t0) : (c1 + t1);
            float w = lo16 ? (c2 + t2) : (c3 + t3);
            float tv = __shfl_xor_sync(0xffffffffu, v, 8);
            float tw = __shfl_xor_sync(0xffffffffu, w, 8);
            float z = ((lane & 8) == 0) ? (v + tv) : (w + tw);
            z += __shfl_xor_sync(0xffffffffu, z, 4);
            z += __shfl_xor_sync(0xffffffffu, z, 2);
            z += __shfl_xor_sync(0xffffffffu, z, 1);

            if ((lane & 7) == 0) {
                int g = ((lane >> 2) & 2) | (lane >> 4);
                int idx = s0g + g;
                if (idx < total) out[idx] = z + b2s;
            }
        }
    }
}

extern "C" void kernel_launch(void* const* d_in, const int* in_sizes, int n_in,
                              void* d_out, int out_size) {
    const float* rec  = (const float*)d_in[0];
    const float* sloc = (const float*)d_in[1];
    const float* emit = (const float*)d_in[2];
    const float* rloc = (const float*)d_in[3];
    const float* W1   = (const float*)d_in[4];
    const float* b1v  = (const float*)d_in[5];
    const float* W2   = (const float*)d_in[6];
    const float* b2v  = (const float*)d_in[7];
    float* out = (float*)d_out;

    int nb1 = in_sizes[0] / (NUM_R * LREC);       // B1
    if (nb1 < 1) nb1 = 1;
    if (nb1 > MAXB1) nb1 = MAXB1;
    int total = out_size;                         // B1*B2 samples
    int b2n = total / nb1;

    int b1shift = -1;
    if (b2n > 0 && (b2n & (b2n - 1)) == 0) {
        b1shift = 0;
        while ((1 << b1shift) != b2n) ++b1shift;
    }

    prep_kernel<<<NUM_R * nb1, 256>>>(W1, rec);

    int blocks = (total + 63) / 64;               // 64 samples per block

    // PDL launch: tof's geometry overlaps prep; fallback to plain launch.
    cudaLaunchConfig_t cfg = {};
    cfg.gridDim  = dim3((unsigned)blocks, 1, 1);
    cfg.blockDim = dim3(256, 1, 1);
    cfg.dynamicSmemBytes = 0;
    cfg.stream = 0;
    cudaLaunchAttribute at[1];
    at[0].id = cudaLaunchAttributeProgrammaticStreamSerialization;
    at[0].val.programmaticStreamSerializationAllowed = 1;
    cfg.attrs = at;
    cfg.numAttrs = 1;
    cudaError_t e = cudaLaunchKernelEx(&cfg, tof_kernel,
                                       sloc, emit, rloc, b1v, W2, b2v, out,
                                       total, b2n, b1shift);
    if (e != cudaSuccess) {
        (void)cudaGetLastError();   // clear sticky error
        tof_kernel<<<blocks, 256>>>(sloc, emit, rloc, b1v, W2, b2v, out,
                                    total, b2n, b1shift);
    }
}